// round 2
// baseline (speedup 1.0000x reference)
#include <cuda_runtime.h>
#include <cstdint>

// Axial attention, fused per-(b,h) CTA, packed f32x2 FFMA (FFMA2) GEMM cores.
// B=16, C=512, C8=64, H=W=64.
//
// SMEM (fp32 words):
//   Xs   [512][64]          32768 w
//   Wt   [64][132]           8448 w   (transposed weight chunk, pitch 132)
//   Qs   [64][64] + Ks[64][64]  (8192 w)  -- aliased by Vst [64][132] (8448 w)
//   S/Pt [64][68]            4352 w   (softmax done in-place)
// total 54016 words = 216064 B

#define NT 512

typedef unsigned long long u64;

union F2U { u64 u; float2 f; };

__device__ __forceinline__ void ffma2(u64& d, u64 a, u64 b) {
    asm("fma.rn.f32x2 %0, %1, %2, %0;" : "+l"(d) : "l"(a), "l"(b));
}
__device__ __forceinline__ u64 add2(u64 a, u64 b) {
    u64 r; asm("add.rn.f32x2 %0, %1, %2;" : "=l"(r) : "l"(a), "l"(b)); return r;
}
__device__ __forceinline__ u64 pack2(float lo, float hi) {
    u64 r; asm("mov.b64 %0, {%1, %2};" : "=l"(r) : "f"(lo), "f"(hi)); return r;
}
__device__ __forceinline__ u64 dup2(float x) { return pack2(x, x); }

extern "C" __global__ void __launch_bounds__(NT, 1)
axial_attn_kernel(const float* __restrict__ x,
                  const float* __restrict__ Wq, const float* __restrict__ bq,
                  const float* __restrict__ Wk, const float* __restrict__ bk,
                  const float* __restrict__ Wv, const float* __restrict__ bv,
                  const float* __restrict__ relh, const float* __restrict__ relw,
                  float* __restrict__ out)
{
    extern __shared__ float smem[];
    float* Xs  = smem;                    // [512][64]
    float* Wt  = Xs + 32768;              // [64][132]
    float* Qs  = Wt + 8448;               // [64][64]
    float* Ks  = Qs + 4096;               // [64][64]
    float* Vst = Qs;                      // [64][132] alias (after phase 2)
    float* S   = Qs + 8448;               // [64][68]
    float* Pt  = S;                       // in-place softmax output [v][w]

    const int h    = blockIdx.x;
    const int b    = blockIdx.y;
    const int t    = threadIdx.x;
    const int warp = t >> 5;
    const int lane = t & 31;
    const int w0   = lane * 2;            // 2 consecutive pixels per thread
    const int o0   = warp * 8;            // 8 output channels per warp

    // ------------------------------------------------------------------
    // Phase 0: load X[b, :, h, :] -> Xs[c][w]
    // ------------------------------------------------------------------
    const float* xbase = x + ((size_t)b * 512 * 4096) + (size_t)h * 64;
    #pragma unroll
    for (int i = t; i < 512 * 16; i += NT) {
        int c  = i >> 4;
        int c4 = i & 15;
        *(float4*)&Xs[c * 64 + c4 * 4] =
            *(const float4*)(xbase + (size_t)c * 4096 + c4 * 4);
    }
    __syncthreads();

    // ------------------------------------------------------------------
    // Phase 1: Q,K projection (128 out-ch x 64 px), FFMA2, pair-dim = d.
    // ------------------------------------------------------------------
    u64 acc[8];
    #pragma unroll
    for (int i = 0; i < 8; i++) acc[i] = 0ULL;

    for (int cc = 0; cc < 8; cc++) {
        // stage transposed weight chunk: Wt[c][o], o<64->Wq, o>=64->Wk
        #pragma unroll
        for (int i = t; i < 64 * 128; i += NT) {
            int c = i & 63;
            int o = i >> 6;
            float v = (o < 64) ? Wq[(size_t)o * 512 + cc * 64 + c]
                               : Wk[(size_t)(o - 64) * 512 + cc * 64 + c];
            Wt[c * 132 + o] = v;
        }
        __syncthreads();

        const float* xrow = &Xs[(cc * 64) * 64 + w0];
        #pragma unroll 8
        for (int c = 0; c < 64; c++) {
            float2 xv = *(const float2*)(xrow + c * 64);
            u64 x0 = dup2(xv.x);
            u64 x1 = dup2(xv.y);
            const float* wr = &Wt[c * 132 + o0];
            ulonglong2 wab = *(const ulonglong2*)(wr);      // pairs (o0,o0+1),(o0+2,o0+3)
            ulonglong2 wcd = *(const ulonglong2*)(wr + 4);  // pairs (o0+4..o0+7)
            ffma2(acc[0], wab.x, x0); ffma2(acc[1], wab.x, x1);
            ffma2(acc[2], wab.y, x0); ffma2(acc[3], wab.y, x1);
            ffma2(acc[4], wcd.x, x0); ffma2(acc[5], wcd.x, x1);
            ffma2(acc[6], wcd.y, x0); ffma2(acc[7], wcd.y, x1);
        }
        __syncthreads();
    }

    // epilogue: bias + rel, store Qs[o][w] / Ks[o][w]
    {
        bool isQ = (o0 < 64);
        #pragma unroll
        for (int p = 0; p < 4; p++) {
            int o = o0 + 2 * p;
            F2U a0; a0.u = acc[2 * p];       // (row o, row o+1) @ w0
            F2U a1; a1.u = acc[2 * p + 1];   // (row o, row o+1) @ w0+1
            if (isQ) {
                float cLo = bq[o]     + relh[(size_t)o * 512 + h];
                float cHi = bq[o + 1] + relh[(size_t)(o + 1) * 512 + h];
                Qs[o * 64 + w0]           = a0.f.x + cLo;
                Qs[(o + 1) * 64 + w0]     = a0.f.y + cHi;
                Qs[o * 64 + w0 + 1]       = a1.f.x + cLo;
                Qs[(o + 1) * 64 + w0 + 1] = a1.f.y + cHi;
            } else {
                int ok = o - 64;
                float bLo = bk[ok], bHi = bk[ok + 1];
                Ks[ok * 64 + w0]           = a0.f.x + bLo + relw[(size_t)ok * 512 + w0];
                Ks[(ok + 1) * 64 + w0]     = a0.f.y + bHi + relw[(size_t)(ok + 1) * 512 + w0];
                Ks[ok * 64 + w0 + 1]       = a1.f.x + bLo + relw[(size_t)ok * 512 + w0 + 1];
                Ks[(ok + 1) * 64 + w0 + 1] = a1.f.y + bHi + relw[(size_t)(ok + 1) * 512 + w0 + 1];
            }
        }
    }
    __syncthreads();

    // ------------------------------------------------------------------
    // Phase 2: scores S[w][v] = sum_c Qs[c][w] * Ks[c][v]
    // ------------------------------------------------------------------
    {
        int sv = (t & 15) * 4;
        int sw = (t >> 4) * 2;
        float s00 = 0.f, s01 = 0.f, s02 = 0.f, s03 = 0.f;
        float s10 = 0.f, s11 = 0.f, s12 = 0.f, s13 = 0.f;
        #pragma unroll 4
        for (int c = 0; c < 64; c++) {
            float4 kv = *(const float4*)&Ks[c * 64 + sv];
            float q0 = Qs[c * 64 + sw];
            float q1 = Qs[c * 64 + sw + 1];
            s00 += q0 * kv.x; s01 += q0 * kv.y; s02 += q0 * kv.z; s03 += q0 * kv.w;
            s10 += q1 * kv.x; s11 += q1 * kv.y; s12 += q1 * kv.z; s13 += q1 * kv.w;
        }
        *(float4*)&S[sw * 68 + sv]       = make_float4(s00, s01, s02, s03);
        *(float4*)&S[(sw + 1) * 68 + sv] = make_float4(s10, s11, s12, s13);
    }
    __syncthreads();

    // ------------------------------------------------------------------
    // Phase 3: softmax over v, IN-PLACE transposed write Pt[v][w] (= S buf)
    // ------------------------------------------------------------------
    {
        float pe0[4], pe1[4];
        #pragma unroll
        for (int it = 0; it < 4; it++) {
            int r = warp + it * 16;
            float a0 = S[r * 68 + lane];
            float a1 = S[r * 68 + lane + 32];
            float m = fmaxf(a0, a1);
            #pragma unroll
            for (int off = 16; off > 0; off >>= 1)
                m = fmaxf(m, __shfl_xor_sync(0xffffffffu, m, off));
            float e0 = __expf(a0 - m);
            float e1 = __expf(a1 - m);
            float s = e0 + e1;
            #pragma unroll
            for (int off = 16; off > 0; off >>= 1)
                s += __shfl_xor_sync(0xffffffffu, s, off);
            float inv = 1.f / s;
            pe0[it] = e0 * inv;
            pe1[it] = e1 * inv;
        }
        __syncthreads();   // all reads of S done
        #pragma unroll
        for (int it = 0; it < 4; it++) {
            int r = warp + it * 16;
            Pt[lane * 68 + r]        = pe0[it];
            Pt[(lane + 32) * 68 + r] = pe1[it];
        }
    }
    __syncthreads();

    // ------------------------------------------------------------------
    // Phase 4: V projection (4 d-chunks of 128) + AV, both FFMA2.
    // ------------------------------------------------------------------
    for (int dc = 0; dc < 4; dc++) {
        const int D = dc * 128;

        u64 vac[8];
        #pragma unroll
        for (int i = 0; i < 8; i++) vac[i] = 0ULL;

        for (int cc = 0; cc < 8; cc++) {
            #pragma unroll
            for (int i = t; i < 64 * 128; i += NT) {
                int c = i & 63;
                int o = i >> 6;
                Wt[c * 132 + o] = Wv[(size_t)(D + o) * 512 + cc * 64 + c];
            }
            __syncthreads();

            const float* xrow = &Xs[(cc * 64) * 64 + w0];
            #pragma unroll 8
            for (int c = 0; c < 64; c++) {
                float2 xv = *(const float2*)(xrow + c * 64);
                u64 x0 = dup2(xv.x);
                u64 x1 = dup2(xv.y);
                const float* wr = &Wt[c * 132 + o0];
                ulonglong2 wab = *(const ulonglong2*)(wr);
                ulonglong2 wcd = *(const ulonglong2*)(wr + 4);
                ffma2(vac[0], wab.x, x0); ffma2(vac[1], wab.x, x1);
                ffma2(vac[2], wab.y, x0); ffma2(vac[3], wab.y, x1);
                ffma2(vac[4], wcd.x, x0); ffma2(vac[5], wcd.x, x1);
                ffma2(vac[6], wcd.y, x0); ffma2(vac[7], wcd.y, x1);
            }
            __syncthreads();
        }

        // bias + store V transposed: Vst[v][o]   (v = pixel index = w0+j)
        #pragma unroll
        for (int p = 0; p < 4; p++) {
            int o = o0 + 2 * p;
            float2 bv2 = *(const float2*)&bv[D + o];
            u64 bp = pack2(bv2.x, bv2.y);
            *(u64*)&Vst[(w0)     * 132 + o] = add2(vac[2 * p],     bp);
            *(u64*)&Vst[(w0 + 1) * 132 + o] = add2(vac[2 * p + 1], bp);
        }
        __syncthreads();

        // AV: out[d][w] = sum_v Pt[v][w] * Vst[v][d]
        u64 oac[8];
        #pragma unroll
        for (int i = 0; i < 8; i++) oac[i] = 0ULL;

        #pragma unroll 8
        for (int v = 0; v < 64; v++) {
            float2 pv = *(const float2*)&Pt[v * 68 + w0];
            u64 p0 = dup2(pv.x);
            u64 p1 = dup2(pv.y);
            const float* vr = &Vst[v * 132 + o0];
            ulonglong2 vab = *(const ulonglong2*)(vr);
            ulonglong2 vcd = *(const ulonglong2*)(vr + 4);
            ffma2(oac[0], vab.x, p0); ffma2(oac[1], vab.x, p1);
            ffma2(oac[2], vab.y, p0); ffma2(oac[3], vab.y, p1);
            ffma2(oac[4], vcd.x, p0); ffma2(oac[5], vcd.x, p1);
            ffma2(oac[6], vcd.y, p0); ffma2(oac[7], vcd.y, p1);
        }

        // write out[b, D+o, h, w0..w0+1] (float2, warp-coalesced 256B)
        #pragma unroll
        for (int p = 0; p < 4; p++) {
            F2U a0; a0.u = oac[2 * p];       // (o, o+1) @ w0
            F2U a1; a1.u = oac[2 * p + 1];   // (o, o+1) @ w0+1
            int oL = D + o0 + 2 * p;
            size_t baseL = (((size_t)b * 512 + oL) * 64 + h) * 64 + w0;
            size_t baseH = baseL + 4096;     // next channel: +64*64
            *(float2*)&out[baseL] = make_float2(a0.f.x, a1.f.x);
            *(float2*)&out[baseH] = make_float2(a0.f.y, a1.f.y);
        }
        __syncthreads();   // Wt / Vst reused next d-chunk
    }
}

extern "C" void kernel_launch(void* const* d_in, const int* in_sizes, int n_in,
                              void* d_out, int out_size)
{
    const float* x    = (const float*)d_in[0];
    const float* Wq   = (const float*)d_in[1];
    const float* bq   = (const float*)d_in[2];
    const float* Wk   = (const float*)d_in[3];
    const float* bk   = (const float*)d_in[4];
    const float* Wv   = (const float*)d_in[5];
    const float* bv   = (const float*)d_in[6];
    const float* relh = (const float*)d_in[7];
    const float* relw = (const float*)d_in[8];
    float* out = (float*)d_out;

    const int smem_bytes = (32768 + 8448 + 8448 + 4352) * 4;   // 216064
    cudaFuncSetAttribute(axial_attn_kernel,
                         cudaFuncAttributeMaxDynamicSharedMemorySize, smem_bytes);

    dim3 grid(64, 16);   // (h, b)
    axial_attn_kernel<<<grid, NT, smem_bytes>>>(x, Wq, bq, Wk, bk, Wv, bv,
                                                relh, relw, out);
}

// round 4
// speedup vs baseline: 2.2138x; 2.2138x over previous
#include <cuda_runtime.h>
#include <cuda_bf16.h>
#include <cstdint>

// ============================================================================
// Axial attention, fused per-(b,h) CTA, legacy mma.sync (HMMA) bf16 3-pass.
// B=16, C=512, C8=64, H=W=64.
// ============================================================================

#define NT 512
#define SWB(o) ((o) ^ (((o) >> 3) & 0x70))

// pre-split weights: rows 0-63 Wq, 64-127 Wk, 128-639 Wv; [640][512] bf16
__device__ __nv_bfloat16 g_wh[640 * 512];
__device__ __nv_bfloat16 g_wl[640 * 512];

// SMEM byte offsets (base 1KB-aligned)
#define XHo 0
#define XLo 65536
#define WHo 131072
#define WLo 147456
#define QSo 163840
#define KSo 180224
#define SSo 196608
#define PHo 214016
#define PLo 222208
#define SMEM_BYTES (230400 + 1024)

__device__ __forceinline__ uint32_t smem_u32(const void* p) {
    uint32_t a;
    asm("{ .reg .u64 t; cvta.to.shared.u64 t, %1; cvt.u32.u64 %0, t; }"
        : "=r"(a) : "l"(p));
    return a;
}
__device__ __forceinline__ void ldsm_x4(uint32_t addr, uint32_t r[4]) {
    asm volatile("ldmatrix.sync.aligned.m8n8.x4.shared.b16 {%0,%1,%2,%3}, [%4];"
                 : "=r"(r[0]), "=r"(r[1]), "=r"(r[2]), "=r"(r[3]) : "r"(addr));
}
__device__ __forceinline__ void ldsm_x4t(uint32_t addr, uint32_t r[4]) {
    asm volatile("ldmatrix.sync.aligned.m8n8.x4.trans.shared.b16 {%0,%1,%2,%3}, [%4];"
                 : "=r"(r[0]), "=r"(r[1]), "=r"(r[2]), "=r"(r[3]) : "r"(addr));
}
__device__ __forceinline__ void mma_bf16(float d[4], const uint32_t a[4],
                                         uint32_t b0, uint32_t b1) {
    asm volatile(
        "mma.sync.aligned.m16n8k16.row.col.f32.bf16.bf16.f32 "
        "{%0,%1,%2,%3}, {%4,%5,%6,%7}, {%8,%9}, {%0,%1,%2,%3};"
        : "+f"(d[0]), "+f"(d[1]), "+f"(d[2]), "+f"(d[3])
        : "r"(a[0]), "r"(a[1]), "r"(a[2]), "r"(a[3]), "r"(b0), "r"(b1));
}
// split fp32 pair -> packed bf16 hi / lo (element a in low half)
__device__ __forceinline__ void split2(float a, float b, unsigned& hi, unsigned& lo) {
    __nv_bfloat16 ha = __float2bfloat16(a), hb = __float2bfloat16(b);
    float la = a - __bfloat162float(ha);
    float lb = b - __bfloat162float(hb);
    hi = (unsigned)__bfloat16_as_ushort(ha) | ((unsigned)__bfloat16_as_ushort(hb) << 16);
    lo = (unsigned)__bfloat16_as_ushort(__float2bfloat16(la))
       | ((unsigned)__bfloat16_as_ushort(__float2bfloat16(lb)) << 16);
}

// fragment address: A-type (row-major [row][64 bf16], SW128) and X-trans B-type.
// lanes 0-7: (row0, cb), 8-15: (row0+8, cb), 16-23: (row0, cb+16), 24-31: (row0+8, cb+16)
__device__ __forceinline__ uint32_t faddrA(uint32_t region, int row0, int colB, int lane) {
    int row = row0 + (lane & 7) + ((lane >> 3) & 1) * 8;
    int cb  = colB + ((lane >> 4) << 4);
    return region + SWB(row * 128 + cb);
}
// P-type B (non-trans over P[w][v]):
// lanes 0-7: (w0, kB), 8-15: (w0, kB+16), 16-23: (w0+8, kB), 24-31: (w0+8, kB+16)
__device__ __forceinline__ uint32_t faddrP(uint32_t region, int w0, int kB, int lane) {
    int row = w0 + (lane & 7) + ((lane >> 4) << 3);
    int cb  = kB + ((lane >> 3) & 1) * 16;
    return region + SWB(row * 128 + cb);
}

// one K=64 chunk: warp tile m32 x n16, A in [128][64] region, B in [512][64] region
__device__ __forceinline__ void gemm_chunk(uint32_t Ab, uint32_t Bb, int brow0,
                                           int m0, int nB, int lane, float acc[2][2][4]) {
    #pragma unroll
    for (int k = 0; k < 4; k++) {
        uint32_t a0[4], a1[4], bb[4];
        ldsm_x4(faddrA(Ab, m0, k * 32, lane), a0);
        ldsm_x4(faddrA(Ab, m0 + 16, k * 32, lane), a1);
        ldsm_x4t(faddrA(Bb, brow0 + k * 16, nB, lane), bb);
        mma_bf16(acc[0][0], a0, bb[0], bb[1]);
        mma_bf16(acc[0][1], a0, bb[2], bb[3]);
        mma_bf16(acc[1][0], a1, bb[0], bb[1]);
        mma_bf16(acc[1][1], a1, bb[2], bb[3]);
    }
}

// ---------------------------------------------------------------------------
// prologue: split W into bf16 hi/lo scratch
// ---------------------------------------------------------------------------
__global__ void __launch_bounds__(256, 4)
split_w_kernel(const float* __restrict__ Wq, const float* __restrict__ Wk,
               const float* __restrict__ Wv)
{
    int gid = blockIdx.x * 256 + threadIdx.x;      // 81920 float4s
    int r = gid >> 7;
    int c = (gid & 127) * 4;
    const float* src = (r < 64)  ? (Wq + (size_t)r * 512 + c)
                     : (r < 128) ? (Wk + (size_t)(r - 64) * 512 + c)
                                 : (Wv + (size_t)(r - 128) * 512 + c);
    float4 v = *(const float4*)src;
    unsigned h0, l0, h1, l1;
    split2(v.x, v.y, h0, l0);
    split2(v.z, v.w, h1, l1);
    size_t off = (size_t)r * 512 + c;
    *(uint2*)(g_wh + off) = make_uint2(h0, h1);
    *(uint2*)(g_wl + off) = make_uint2(l0, l1);
}

// ---------------------------------------------------------------------------
// main fused kernel
// ---------------------------------------------------------------------------
extern "C" __global__ void __launch_bounds__(NT, 1)
axial_attn_kernel(const float* __restrict__ x,
                  const float* __restrict__ bq, const float* __restrict__ bk,
                  const float* __restrict__ bv,
                  const float* __restrict__ relh, const float* __restrict__ relw,
                  float* __restrict__ out)
{
    extern __shared__ char smraw[];
    char* smb = (char*)(((uintptr_t)smraw + 1023) & ~(uintptr_t)1023);
    const uint32_t sb = smem_u32(smb);

    const uint32_t XH = sb + XHo, XL = sb + XLo;
    const uint32_t WH = sb + WHo, WL = sb + WLo;
    const uint32_t PH = sb + PHo, PL = sb + PLo;
    float* Qs = (float*)(smb + QSo);   // [64][64]
    float* Ks = (float*)(smb + KSo);   // [64][64]
    float* S  = (float*)(smb + SSo);   // [64][68]

    const int hRow = blockIdx.x;
    const int b    = blockIdx.y;
    const int t    = threadIdx.x;
    const int wid  = t >> 5;
    const int lane = t & 31;
    const int wm   = wid >> 2;         // m-tile 0..3 (32 rows)
    const int wn   = wid & 3;          // n-tile 0..3 (16 cols)
    const int m0   = wm * 32;
    const int nB   = wn * 32;          // n byte offset (16 cols * 2B)

    // ---- Phase 0: load + split X[b,:,hRow,:] -> XH/XL swizzled [c][w] ----
    const float* xb = x + (size_t)b * 512 * 4096 + (size_t)hRow * 64;
    #pragma unroll 4
    for (int i = t; i < 8192; i += NT) {
        int c = i >> 4, c4 = i & 15;
        float4 v = *(const float4*)(xb + (size_t)c * 4096 + c4 * 4);
        unsigned h0, l0, h1, l1;
        split2(v.x, v.y, h0, l0);
        split2(v.z, v.w, h1, l1);
        int off = SWB(c * 128 + c4 * 8);
        *(uint2*)(smb + XHo + off) = make_uint2(h0, h1);
        *(uint2*)(smb + XLo + off) = make_uint2(l0, l1);
    }
    __syncthreads();

    // ---- Phase 1: QK projection, HMMA, 3-pass ----
    float acc[2][2][4];
    #pragma unroll
    for (int i = 0; i < 2; i++)
        #pragma unroll
        for (int j = 0; j < 2; j++)
            #pragma unroll
            for (int e = 0; e < 4; e++) acc[i][j][e] = 0.f;

    for (int cc = 0; cc < 8; cc++) {
        // stage W chunk rows 0..127 (Q,K), cols cc*64..+64, both halves
        #pragma unroll
        for (int i = t; i < 2048; i += NT) {
            int half = i >> 10, idx = i & 1023;
            int row = idx >> 3, cb = (idx & 7) << 4;
            const __nv_bfloat16* src =
                (half ? g_wl : g_wh) + (size_t)row * 512 + cc * 64 + (cb >> 1);
            *(uint4*)(smb + (half ? WLo : WHo) + SWB(row * 128 + cb)) =
                *(const uint4*)src;
        }
        __syncthreads();
        gemm_chunk(WH, XH, cc * 64, m0, nB, lane, acc);
        gemm_chunk(WH, XL, cc * 64, m0, nB, lane, acc);
        gemm_chunk(WL, XH, cc * 64, m0, nB, lane, acc);
        __syncthreads();
    }

    // epilogue: bias + rel -> Qs / Ks fp32
    #pragma unroll
    for (int mi = 0; mi < 2; mi++) {
        #pragma unroll
        for (int ni = 0; ni < 2; ni++) {
            int row = m0 + mi * 16 + (lane >> 2);
            int col = wn * 16 + ni * 8 + (lane & 3) * 2;
            float d0 = acc[mi][ni][0], d1 = acc[mi][ni][1];
            float d2 = acc[mi][ni][2], d3 = acc[mi][ni][3];
            if (row < 64) {
                float a = bq[row] + relh[(size_t)row * 512 + hRow];
                *(float2*)&Qs[row * 64 + col] = make_float2(d0 + a, d1 + a);
                float a2 = bq[row + 8] + relh[(size_t)(row + 8) * 512 + hRow];
                *(float2*)&Qs[(row + 8) * 64 + col] = make_float2(d2 + a2, d3 + a2);
            } else {
                int ok = row - 64;
                float bb = bk[ok];
                *(float2*)&Ks[ok * 64 + col] = make_float2(
                    d0 + bb + relw[(size_t)ok * 512 + col],
                    d1 + bb + relw[(size_t)ok * 512 + col + 1]);
                float bb2 = bk[ok + 8];
                *(float2*)&Ks[(ok + 8) * 64 + col] = make_float2(
                    d2 + bb2 + relw[(size_t)(ok + 8) * 512 + col],
                    d3 + bb2 + relw[(size_t)(ok + 8) * 512 + col + 1]);
            }
        }
    }
    __syncthreads();

    // ---- Phase 2: scores S[w][v] (SIMT) ----
    {
        int sv = (t & 15) * 4;
        int sw = (t >> 4) * 2;
        float s00 = 0.f, s01 = 0.f, s02 = 0.f, s03 = 0.f;
        float s10 = 0.f, s11 = 0.f, s12 = 0.f, s13 = 0.f;
        #pragma unroll 4
        for (int c = 0; c < 64; c++) {
            float4 kv = *(const float4*)&Ks[c * 64 + sv];
            float q0 = Qs[c * 64 + sw];
            float q1 = Qs[c * 64 + sw + 1];
            s00 += q0 * kv.x; s01 += q0 * kv.y; s02 += q0 * kv.z; s03 += q0 * kv.w;
            s10 += q1 * kv.x; s11 += q1 * kv.y; s12 += q1 * kv.z; s13 += q1 * kv.w;
        }
        *(float4*)&S[sw * 68 + sv]       = make_float4(s00, s01, s02, s03);
        *(float4*)&S[(sw + 1) * 68 + sv] = make_float4(s10, s11, s12, s13);
    }
    __syncthreads();

    // ---- Phase 3: softmax -> P bf16 hi/lo [w][v] swizzled ----
    #pragma unroll
    for (int it = 0; it < 4; it++) {
        int r = wid + it * 16;
        float a0 = S[r * 68 + lane];
        float a1 = S[r * 68 + lane + 32];
        float m = fmaxf(a0, a1);
        #pragma unroll
        for (int off = 16; off > 0; off >>= 1)
            m = fmaxf(m, __shfl_xor_sync(0xffffffffu, m, off));
        float e0 = __expf(a0 - m);
        float e1 = __expf(a1 - m);
        float s = e0 + e1;
        #pragma unroll
        for (int off = 16; off > 0; off >>= 1)
            s += __shfl_xor_sync(0xffffffffu, s, off);
        float inv = 1.f / s;
        float p0 = e0 * inv, p1 = e1 * inv;
        __nv_bfloat16 h0 = __float2bfloat16(p0);
        __nv_bfloat16 h1 = __float2bfloat16(p1);
        unsigned short lo0 = __bfloat16_as_ushort(__float2bfloat16(p0 - __bfloat162float(h0)));
        unsigned short lo1 = __bfloat16_as_ushort(__float2bfloat16(p1 - __bfloat162float(h1)));
        int o0 = SWB(r * 128 + lane * 2);
        int o1 = SWB(r * 128 + (lane + 32) * 2);
        *(unsigned short*)(smb + PHo + o0) = __bfloat16_as_ushort(h0);
        *(unsigned short*)(smb + PLo + o0) = lo0;
        *(unsigned short*)(smb + PHo + o1) = __bfloat16_as_ushort(h1);
        *(unsigned short*)(smb + PLo + o1) = lo1;
    }

    // ---- Phase 4: V projection + AV per 128-channel chunk ----
    for (int dc = 0; dc < 4; dc++) {
        float vac[2][2][4];
        #pragma unroll
        for (int i = 0; i < 2; i++)
            #pragma unroll
            for (int j = 0; j < 2; j++)
                #pragma unroll
                for (int e = 0; e < 4; e++) vac[i][j][e] = 0.f;

        const int wrow = 128 + dc * 128;
        for (int cc = 0; cc < 8; cc++) {
            #pragma unroll
            for (int i = t; i < 2048; i += NT) {
                int half = i >> 10, idx = i & 1023;
                int row = idx >> 3, cb = (idx & 7) << 4;
                const __nv_bfloat16* src =
                    (half ? g_wl : g_wh) + (size_t)(wrow + row) * 512 + cc * 64 + (cb >> 1);
                *(uint4*)(smb + (half ? WLo : WHo) + SWB(row * 128 + cb)) =
                    *(const uint4*)src;
            }
            __syncthreads();
            gemm_chunk(WH, XH, cc * 64, m0, nB, lane, vac);
            gemm_chunk(WH, XL, cc * 64, m0, nB, lane, vac);
            gemm_chunk(WL, XH, cc * 64, m0, nB, lane, vac);
            __syncthreads();
        }

        // epilogue: +bias, split to bf16, store into VH/VL (alias WH/WL) [d][v]
        #pragma unroll
        for (int mi = 0; mi < 2; mi++) {
            #pragma unroll
            for (int ni = 0; ni < 2; ni++) {
                int row = m0 + mi * 16 + (lane >> 2);
                int col = wn * 16 + ni * 8 + (lane & 3) * 2;
                float b0f = bv[dc * 128 + row];
                float b1f = bv[dc * 128 + row + 8];
                unsigned h0, l0, h1, l1;
                split2(vac[mi][ni][0] + b0f, vac[mi][ni][1] + b0f, h0, l0);
                split2(vac[mi][ni][2] + b1f, vac[mi][ni][3] + b1f, h1, l1);
                int off0 = SWB(row * 128 + col * 2);
                int off1 = SWB((row + 8) * 128 + col * 2);
                *(unsigned*)(smb + WHo + off0) = h0;
                *(unsigned*)(smb + WLo + off0) = l0;
                *(unsigned*)(smb + WHo + off1) = h1;
                *(unsigned*)(smb + WLo + off1) = l1;
            }
        }
        __syncthreads();

        // AV: out[d][w] = sum_v V[d][v] P[w][v]  (A=V, B=P via non-trans ldmatrix)
        float oac[2][2][4];
        #pragma unroll
        for (int i = 0; i < 2; i++)
            #pragma unroll
            for (int j = 0; j < 2; j++)
                #pragma unroll
                for (int e = 0; e < 4; e++) oac[i][j][e] = 0.f;

        #pragma unroll
        for (int pass = 0; pass < 3; pass++) {
            uint32_t Ab = (pass == 2) ? WL : WH;
            uint32_t Bb = (pass == 1) ? PL : PH;
            #pragma unroll
            for (int k = 0; k < 4; k++) {
                uint32_t a0[4], a1[4], bb[4];
                ldsm_x4(faddrA(Ab, m0, k * 32, lane), a0);
                ldsm_x4(faddrA(Ab, m0 + 16, k * 32, lane), a1);
                ldsm_x4(faddrP(Bb, wn * 16, k * 32, lane), bb);
                mma_bf16(oac[0][0], a0, bb[0], bb[1]);
                mma_bf16(oac[0][1], a0, bb[2], bb[3]);
                mma_bf16(oac[1][0], a1, bb[0], bb[1]);
                mma_bf16(oac[1][1], a1, bb[2], bb[3]);
            }
        }

        // write out[b, dc*128+row, hRow, col..col+1]
        #pragma unroll
        for (int mi = 0; mi < 2; mi++) {
            #pragma unroll
            for (int ni = 0; ni < 2; ni++) {
                int row = m0 + mi * 16 + (lane >> 2);
                int col = wn * 16 + ni * 8 + (lane & 3) * 2;
                size_t base0 = (((size_t)b * 512 + dc * 128 + row) * 64 + hRow) * 64 + col;
                size_t base1 = base0 + 8 * 4096;   // row+8 channels
                *(float2*)&out[base0] = make_float2(oac[mi][ni][0], oac[mi][ni][1]);
                *(float2*)&out[base1] = make_float2(oac[mi][ni][2], oac[mi][ni][3]);
            }
        }
        __syncthreads();
    }
}

extern "C" void kernel_launch(void* const* d_in, const int* in_sizes, int n_in,
                              void* d_out, int out_size)
{
    const float* x    = (const float*)d_in[0];
    const float* Wq   = (const float*)d_in[1];
    const float* bq   = (const float*)d_in[2];
    const float* Wk   = (const float*)d_in[3];
    const float* bk   = (const float*)d_in[4];
    const float* Wv   = (const float*)d_in[5];
    const float* bv   = (const float*)d_in[6];
    const float* relh = (const float*)d_in[7];
    const float* relw = (const float*)d_in[8];
    float* out = (float*)d_out;

    cudaFuncSetAttribute(axial_attn_kernel,
                         cudaFuncAttributeMaxDynamicSharedMemorySize, SMEM_BYTES);

    split_w_kernel<<<320, 256>>>(Wq, Wk, Wv);
    dim3 grid(64, 16);   // (h, b)
    axial_attn_kernel<<<grid, NT, SMEM_BYTES>>>(x, bq, bk, bv, relh, relw, out);
}

// round 5
// speedup vs baseline: 2.6366x; 1.1910x over previous
#include <cuda_runtime.h>
#include <cuda_bf16.h>
#include <cstdint>

// ============================================================================
// Axial attention, fused per-(b,h) CTA. HMMA bf16 3-pass with a continuous
// cp.async triple-buffered weight pipeline across all GEMM phases.
// B=16, C=512, C8=64, H=W=64.
// ============================================================================

#define NT 512
#define SWB(o)  ((o) ^ (((o) >> 3) & 0x70))   // 128B-pitch swizzle
#define SW64(o) ((o) ^ (((o) >> 3) & 0x30))   // 64B-pitch swizzle

// pre-split weights: rows 0-63 Wq, 64-127 Wk, 128-639 Wv; [640][512] bf16
__device__ __nv_bfloat16 g_wh[640 * 512];
__device__ __nv_bfloat16 g_wl[640 * 512];

// SMEM byte offsets (from 1KB-aligned base)
#define XHo 0                   // X hi  [512][64] bf16, 128B pitch SW128
#define XLo 65536               // X lo
#define WBo 131072              // W ring: 3 x 16384 (each: hi 8192 + lo 8192)
#define Co  180224              // ph1-2: Qs[64][64]f32 + Ks ; ph4: VH+VL bf16
#define PHo 212992              // P hi [64][64] bf16 128B pitch
#define PLo 221184              // P lo
#define SMEM_BYTES (229376 + 1024)

__device__ __forceinline__ uint32_t smem_u32(const void* p) {
    uint32_t a;
    asm("{ .reg .u64 t; cvta.to.shared.u64 t, %1; cvt.u32.u64 %0, t; }"
        : "=r"(a) : "l"(p));
    return a;
}
__device__ __forceinline__ void cpasync16(uint32_t dst, const void* src) {
    asm volatile("cp.async.cg.shared.global [%0], [%1], 16;" :: "r"(dst), "l"(src));
}
__device__ __forceinline__ void cpcommit() {
    asm volatile("cp.async.commit_group;" ::: "memory");
}
__device__ __forceinline__ void cpwait1() {
    asm volatile("cp.async.wait_group 1;" ::: "memory");
}
__device__ __forceinline__ void cpwait0() {
    asm volatile("cp.async.wait_group 0;" ::: "memory");
}
__device__ __forceinline__ void ldsm_x4(uint32_t addr, uint32_t r[4]) {
    asm volatile("ldmatrix.sync.aligned.m8n8.x4.shared.b16 {%0,%1,%2,%3}, [%4];"
                 : "=r"(r[0]), "=r"(r[1]), "=r"(r[2]), "=r"(r[3]) : "r"(addr));
}
__device__ __forceinline__ void ldsm_x4t(uint32_t addr, uint32_t r[4]) {
    asm volatile("ldmatrix.sync.aligned.m8n8.x4.trans.shared.b16 {%0,%1,%2,%3}, [%4];"
                 : "=r"(r[0]), "=r"(r[1]), "=r"(r[2]), "=r"(r[3]) : "r"(addr));
}
__device__ __forceinline__ void mma_bf16(float d[4], const uint32_t a[4],
                                         uint32_t b0, uint32_t b1) {
    asm volatile(
        "mma.sync.aligned.m16n8k16.row.col.f32.bf16.bf16.f32 "
        "{%0,%1,%2,%3}, {%4,%5,%6,%7}, {%8,%9}, {%0,%1,%2,%3};"
        : "+f"(d[0]), "+f"(d[1]), "+f"(d[2]), "+f"(d[3])
        : "r"(a[0]), "r"(a[1]), "r"(a[2]), "r"(a[3]), "r"(b0), "r"(b1));
}
__device__ __forceinline__ void split2(float a, float b, unsigned& hi, unsigned& lo) {
    __nv_bfloat16 ha = __float2bfloat16(a), hb = __float2bfloat16(b);
    float la = a - __bfloat162float(ha);
    float lb = b - __bfloat162float(hb);
    hi = (unsigned)__bfloat16_as_ushort(ha) | ((unsigned)__bfloat16_as_ushort(hb) << 16);
    lo = (unsigned)__bfloat16_as_ushort(__float2bfloat16(la))
       | ((unsigned)__bfloat16_as_ushort(__float2bfloat16(lb)) << 16);
}

// A fragment addr, 128B-pitch SW128 region (X, V, P-as-A)
__device__ __forceinline__ uint32_t faddrA(uint32_t region, int row0, int colB, int lane) {
    int row = row0 + (lane & 7) + ((lane >> 3) & 1) * 8;
    int cb  = colB + ((lane >> 4) << 4);
    return region + SWB(row * 128 + cb);
}
// A fragment addr, 64B-pitch SW64 region (W ring buffers)
__device__ __forceinline__ uint32_t faddrW(uint32_t region, int row0, int colB, int lane) {
    int row = row0 + (lane & 7) + ((lane >> 3) & 1) * 8;
    int cb  = colB + ((lane >> 4) << 4);
    return region + SW64(row * 64 + cb);
}
// P as B (non-trans), 128B pitch
__device__ __forceinline__ uint32_t faddrP(uint32_t region, int w0, int kB, int lane) {
    int row = w0 + (lane & 7) + ((lane >> 4) << 3);
    int cb  = kB + ((lane >> 3) & 1) * 16;
    return region + SWB(row * 128 + cb);
}

// ---------------------------------------------------------------------------
// prologue: split W into bf16 hi/lo scratch
// ---------------------------------------------------------------------------
__global__ void __launch_bounds__(256, 4)
split_w_kernel(const float* __restrict__ Wq, const float* __restrict__ Wk,
               const float* __restrict__ Wv)
{
    int gid = blockIdx.x * 256 + threadIdx.x;      // 81920 float4s
    int r = gid >> 7;
    int c = (gid & 127) * 4;
    const float* src = (r < 64)  ? (Wq + (size_t)r * 512 + c)
                     : (r < 128) ? (Wk + (size_t)(r - 64) * 512 + c)
                                 : (Wv + (size_t)(r - 128) * 512 + c);
    float4 v = *(const float4*)src;
    unsigned h0, l0, h1, l1;
    split2(v.x, v.y, h0, l0);
    split2(v.z, v.w, h1, l1);
    size_t off = (size_t)r * 512 + c;
    *(uint2*)(g_wh + off) = make_uint2(h0, h1);
    *(uint2*)(g_wl + off) = make_uint2(l0, l1);
}

// global W-stream chunk g (0..79): g<16 -> QK rows 0..127, cols g*32
//                                  g>=16 -> V rows 128+((g-16)>>4)*128, cols ((g-16)&15)*32
__device__ __forceinline__ void issueW(uint32_t sb, int g, int t) {
    int Rb, c0;
    if (g < 16) { Rb = 0; c0 = g * 32; }
    else        { int v = g - 16; Rb = 128 + (v >> 4) * 128; c0 = (v & 15) * 32; }
    uint32_t buf = sb + WBo + (g % 3) * 16384;
    #pragma unroll
    for (int j = t; j < 1024; j += NT) {
        int half = j >> 9;
        int u    = j & 511;
        int row  = u >> 2;
        int seg  = u & 3;                 // 16B segment within 64B row
        const __nv_bfloat16* src =
            (half ? g_wl : g_wh) + (size_t)(Rb + row) * 512 + c0 + seg * 8;
        cpasync16(buf + half * 8192 + SW64(row * 64 + seg * 16), src);
    }
    cpcommit();
}

// one K=32 chunk, 3-pass split: acc += W[0:128, 32] * X[rows, :64]^T
__device__ __forceinline__ void mma_chunk(uint32_t wbuf, uint32_t XH, uint32_t XL,
                                          int xrow0, int m0, int nB, int lane,
                                          float acc[2][2][4]) {
    #pragma unroll
    for (int pass = 0; pass < 3; pass++) {
        uint32_t Wb = wbuf + ((pass == 2) ? 8192 : 0);   // lo W on pass 2
        uint32_t Xb = (pass == 1) ? XL : XH;             // lo X on pass 1
        #pragma unroll
        for (int ks = 0; ks < 2; ks++) {
            uint32_t a0[4], a1[4], bb[4];
            ldsm_x4 (faddrW(Wb, m0,      ks * 32, lane), a0);
            ldsm_x4 (faddrW(Wb, m0 + 16, ks * 32, lane), a1);
            ldsm_x4t(faddrA(Xb, xrow0 + ks * 16, nB, lane), bb);
            mma_bf16(acc[0][0], a0, bb[0], bb[1]);
            mma_bf16(acc[0][1], a0, bb[2], bb[3]);
            mma_bf16(acc[1][0], a1, bb[0], bb[1]);
            mma_bf16(acc[1][1], a1, bb[2], bb[3]);
        }
    }
}

// ---------------------------------------------------------------------------
// main fused kernel
// ---------------------------------------------------------------------------
extern "C" __global__ void __launch_bounds__(NT, 1)
axial_attn_kernel(const float* __restrict__ x,
                  const float* __restrict__ bq, const float* __restrict__ bk,
                  const float* __restrict__ bv,
                  const float* __restrict__ relh, const float* __restrict__ relw,
                  float* __restrict__ out)
{
    extern __shared__ char smraw[];
    char* smb = (char*)(((uintptr_t)smraw + 1023) & ~(uintptr_t)1023);
    const uint32_t sb = smem_u32(smb);

    const uint32_t XH = sb + XHo, XL = sb + XLo;
    const uint32_t PH = sb + PHo, PL = sb + PLo;
    const uint32_t VH = sb + Co,  VL = sb + Co + 16384;
    float* Qs = (float*)(smb + Co);            // [64][64] (phases 1-2)
    float* Ks = (float*)(smb + Co + 16384);

    const int hRow = blockIdx.x;
    const int b    = blockIdx.y;
    const int t    = threadIdx.x;
    const int wid  = t >> 5;
    const int lane = t & 31;
    const int m0   = (wid >> 2) * 32;   // warp m-tile
    const int wn   = wid & 3;
    const int nB   = wn * 32;           // warp n-tile byte offset (16 cols)

    // prefetch W chunks 0,1 (overlap with X load)
    issueW(sb, 0, t);
    issueW(sb, 1, t);

    // ---- Phase 0: load + split X[b,:,hRow,:] -> XH/XL swizzled [c][w] ----
    const float* xb = x + (size_t)b * 512 * 4096 + (size_t)hRow * 64;
    #pragma unroll 4
    for (int i = t; i < 8192; i += NT) {
        int c = i >> 4, c4 = i & 15;
        float4 v = *(const float4*)(xb + (size_t)c * 4096 + c4 * 4);
        unsigned h0, l0, h1, l1;
        split2(v.x, v.y, h0, l0);
        split2(v.z, v.w, h1, l1);
        int off = SWB(c * 128 + c4 * 8);
        *(uint2*)(smb + XHo + off) = make_uint2(h0, h1);
        *(uint2*)(smb + XLo + off) = make_uint2(l0, l1);
    }
    __syncthreads();

    // ---- Phase 1: QK projection, 16 chunks pipelined ----
    float acc[2][2][4];
    #pragma unroll
    for (int i = 0; i < 2; i++)
        #pragma unroll
        for (int j = 0; j < 2; j++)
            #pragma unroll
            for (int e = 0; e < 4; e++) acc[i][j][e] = 0.f;

    for (int g = 0; g < 16; g++) {
        cpwait1();
        __syncthreads();
        issueW(sb, g + 2, t);                     // up to chunk 17 (V stream)
        mma_chunk(sb + WBo + (g % 3) * 16384, XH, XL, g * 32, m0, nB, lane, acc);
    }

    // epilogue: bias + rel -> Qs / Ks fp32
    #pragma unroll
    for (int mi = 0; mi < 2; mi++) {
        #pragma unroll
        for (int ni = 0; ni < 2; ni++) {
            int row = m0 + mi * 16 + (lane >> 2);
            int col = wn * 16 + ni * 8 + (lane & 3) * 2;
            float d0 = acc[mi][ni][0], d1 = acc[mi][ni][1];
            float d2 = acc[mi][ni][2], d3 = acc[mi][ni][3];
            if (row < 64) {
                float a  = bq[row] + relh[(size_t)row * 512 + hRow];
                float a2 = bq[row + 8] + relh[(size_t)(row + 8) * 512 + hRow];
                *(float2*)&Qs[row * 64 + col]       = make_float2(d0 + a,  d1 + a);
                *(float2*)&Qs[(row + 8) * 64 + col] = make_float2(d2 + a2, d3 + a2);
            } else {
                int ok = row - 64;
                float bb1 = bk[ok], bb2 = bk[ok + 8];
                *(float2*)&Ks[ok * 64 + col] = make_float2(
                    d0 + bb1 + relw[(size_t)ok * 512 + col],
                    d1 + bb1 + relw[(size_t)ok * 512 + col + 1]);
                *(float2*)&Ks[(ok + 8) * 64 + col] = make_float2(
                    d2 + bb2 + relw[(size_t)(ok + 8) * 512 + col],
                    d3 + bb2 + relw[(size_t)(ok + 8) * 512 + col + 1]);
            }
        }
    }
    __syncthreads();

    // ---- Phase 2+3: scores + softmax in registers, write P bf16 hi/lo ----
    {
        int tv = t & 15, tg = t >> 4;
        int sv = tv * 4, sw = tg * 2;
        float s0[4] = {0.f, 0.f, 0.f, 0.f};
        float s1[4] = {0.f, 0.f, 0.f, 0.f};
        #pragma unroll 4
        for (int c = 0; c < 64; c++) {
            float4 kv = *(const float4*)&Ks[c * 64 + sv];
            float q0 = Qs[c * 64 + sw];
            float q1 = Qs[c * 64 + sw + 1];
            s0[0] += q0 * kv.x; s0[1] += q0 * kv.y; s0[2] += q0 * kv.z; s0[3] += q0 * kv.w;
            s1[0] += q1 * kv.x; s1[1] += q1 * kv.y; s1[2] += q1 * kv.z; s1[3] += q1 * kv.w;
        }
        // row-wise softmax across the 16 threads sharing tg (same warp half)
        float m0v = fmaxf(fmaxf(s0[0], s0[1]), fmaxf(s0[2], s0[3]));
        float m1v = fmaxf(fmaxf(s1[0], s1[1]), fmaxf(s1[2], s1[3]));
        #pragma unroll
        for (int off = 8; off > 0; off >>= 1) {
            m0v = fmaxf(m0v, __shfl_xor_sync(0xffffffffu, m0v, off));
            m1v = fmaxf(m1v, __shfl_xor_sync(0xffffffffu, m1v, off));
        }
        float e0[4], e1[4], t0 = 0.f, t1 = 0.f;
        #pragma unroll
        for (int j = 0; j < 4; j++) {
            e0[j] = __expf(s0[j] - m0v); t0 += e0[j];
            e1[j] = __expf(s1[j] - m1v); t1 += e1[j];
        }
        #pragma unroll
        for (int off = 8; off > 0; off >>= 1) {
            t0 += __shfl_xor_sync(0xffffffffu, t0, off);
            t1 += __shfl_xor_sync(0xffffffffu, t1, off);
        }
        float i0 = 1.f / t0, i1 = 1.f / t1;
        unsigned h0a, l0a, h0b, l0b, h1a, l1a, h1b, l1b;
        split2(e0[0] * i0, e0[1] * i0, h0a, l0a);
        split2(e0[2] * i0, e0[3] * i0, h0b, l0b);
        split2(e1[0] * i1, e1[1] * i1, h1a, l1a);
        split2(e1[2] * i1, e1[3] * i1, h1b, l1b);
        int of0 = SWB(sw * 128 + sv * 2);
        int of1 = SWB((sw + 1) * 128 + sv * 2);
        *(uint2*)(smb + PHo + of0) = make_uint2(h0a, h0b);
        *(uint2*)(smb + PLo + of0) = make_uint2(l0a, l0b);
        *(uint2*)(smb + PHo + of1) = make_uint2(h1a, h1b);
        *(uint2*)(smb + PLo + of1) = make_uint2(l1a, l1b);
    }
    // (visibility of P and of Qs/Ks-region reuse covered by loop-top barrier)

    // ---- Phase 4: V projection + AV, 64 chunks pipelined ----
    float vac[2][2][4];
    for (int g = 16; g < 80; g++) {
        int local = g - 16;
        int cc = local & 15;
        if (cc == 0) {
            #pragma unroll
            for (int i = 0; i < 2; i++)
                #pragma unroll
                for (int j = 0; j < 2; j++)
                    #pragma unroll
                    for (int e = 0; e < 4; e++) vac[i][j][e] = 0.f;
        }
        if (g >= 78) cpwait0(); else cpwait1();
        __syncthreads();
        if (g + 2 < 80) issueW(sb, g + 2, t);
        mma_chunk(sb + WBo + (g % 3) * 16384, XH, XL, cc * 32, m0, nB, lane, vac);

        if (cc == 15) {
            int dc = local >> 4;
            __syncthreads();   // all mma reads of this dc done before C overwrite
            // epilogue: +bias, split bf16 -> VH/VL [d][v]
            #pragma unroll
            for (int mi = 0; mi < 2; mi++) {
                #pragma unroll
                for (int ni = 0; ni < 2; ni++) {
                    int row = m0 + mi * 16 + (lane >> 2);
                    int col = wn * 16 + ni * 8 + (lane & 3) * 2;
                    float b0f = bv[dc * 128 + row];
                    float b1f = bv[dc * 128 + row + 8];
                    unsigned h0, l0, h1, l1;
                    split2(vac[mi][ni][0] + b0f, vac[mi][ni][1] + b0f, h0, l0);
                    split2(vac[mi][ni][2] + b1f, vac[mi][ni][3] + b1f, h1, l1);
                    int off0 = SWB(row * 128 + col * 2);
                    int off1 = SWB((row + 8) * 128 + col * 2);
                    *(unsigned*)(smb + Co + off0)         = h0;
                    *(unsigned*)(smb + Co + 16384 + off0) = l0;
                    *(unsigned*)(smb + Co + off1)         = h1;
                    *(unsigned*)(smb + Co + 16384 + off1) = l1;
                }
            }
            __syncthreads();

            // AV: out[d][w] = sum_v V[d][v] P[w][v]
            float oac[2][2][4];
            #pragma unroll
            for (int i = 0; i < 2; i++)
                #pragma unroll
                for (int j = 0; j < 2; j++)
                    #pragma unroll
                    for (int e = 0; e < 4; e++) oac[i][j][e] = 0.f;

            #pragma unroll
            for (int pass = 0; pass < 3; pass++) {
                uint32_t Ab = (pass == 2) ? VL : VH;
                uint32_t Bb = (pass == 1) ? PL : PH;
                #pragma unroll
                for (int k = 0; k < 4; k++) {
                    uint32_t a0[4], a1[4], bbf[4];
                    ldsm_x4(faddrA(Ab, m0,      k * 32, lane), a0);
                    ldsm_x4(faddrA(Ab, m0 + 16, k * 32, lane), a1);
                    ldsm_x4(faddrP(Bb, wn * 16, k * 32, lane), bbf);
                    mma_bf16(oac[0][0], a0, bbf[0], bbf[1]);
                    mma_bf16(oac[0][1], a0, bbf[2], bbf[3]);
                    mma_bf16(oac[1][0], a1, bbf[0], bbf[1]);
                    mma_bf16(oac[1][1], a1, bbf[2], bbf[3]);
                }
            }

            #pragma unroll
            for (int mi = 0; mi < 2; mi++) {
                #pragma unroll
                for (int ni = 0; ni < 2; ni++) {
                    int row = m0 + mi * 16 + (lane >> 2);
                    int col = wn * 16 + ni * 8 + (lane & 3) * 2;
                    size_t base0 = (((size_t)b * 512 + dc * 128 + row) * 64 + hRow) * 64 + col;
                    size_t base1 = base0 + 8 * 4096;
                    *(float2*)&out[base0] = make_float2(oac[mi][ni][0], oac[mi][ni][1]);
                    *(float2*)&out[base1] = make_float2(oac[mi][ni][2], oac[mi][ni][3]);
                }
            }
        }
    }
}

extern "C" void kernel_launch(void* const* d_in, const int* in_sizes, int n_in,
                              void* d_out, int out_size)
{
    const float* x    = (const float*)d_in[0];
    const float* Wq   = (const float*)d_in[1];
    const float* bq   = (const float*)d_in[2];
    const float* Wk   = (const float*)d_in[3];
    const float* bk   = (const float*)d_in[4];
    const float* Wv   = (const float*)d_in[5];
    const float* bv   = (const float*)d_in[6];
    const float* relh = (const float*)d_in[7];
    const float* relw = (const float*)d_in[8];
    float* out = (float*)d_out;

    cudaFuncSetAttribute(axial_attn_kernel,
                         cudaFuncAttributeMaxDynamicSharedMemorySize, SMEM_BYTES);

    split_w_kernel<<<320, 256>>>(Wq, Wk, Wv);
    dim3 grid(64, 16);   // (h, b)
    axial_attn_kernel<<<grid, NT, SMEM_BYTES>>>(x, bq, bk, bv, relh, relw, out);
}